// round 11
// baseline (speedup 1.0000x reference)
#include <cuda_runtime.h>
#include <cuda_bf16.h>
#include <cstdint>

#define B_ 8
#define N_ 2048
#define F_ 64
#define HID_ 32
#define BN_TOTAL (B_*N_)
#define GRP 4                                 // batches per L2-resident group

// ---------------- scratch ----------------
__device__ float g_dm[BN_TOTAL];
__device__ float g_add[BN_TOTAL];
__device__ float g_Ya[BN_TOTAL*HID_];                // fp32 Y ping
__device__ float g_Yb[BN_TOTAL*HID_];                // fp32 Y pong
__device__ float g_pool[B_*HID_];                    // global max pool (relu>=0, int-ordered)
__device__ __nv_bfloat16 g_Thi_a[B_*HID_*N_];        // Y^T bf16 hi ping  [b][f][n]
__device__ __nv_bfloat16 g_Tlo_a[B_*HID_*N_];
__device__ __nv_bfloat16 g_Thi_b[B_*HID_*N_];        // pong
__device__ __nv_bfloat16 g_Tlo_b[B_*HID_*N_];
__device__ __nv_bfloat16 g_Ahi[(size_t)BN_TOTAL*N_]; // A bf16 hi  [b][n][k]
__device__ __nv_bfloat16 g_Alo[(size_t)BN_TOTAL*N_]; // A bf16 lo

// ---------------- helpers ----------------
__device__ __forceinline__ void mma16816(float* c, const uint32_t* a, const uint32_t* b) {
    asm volatile("mma.sync.aligned.m16n8k16.row.col.f32.bf16.bf16.f32 "
        "{%0,%1,%2,%3}, {%4,%5,%6,%7}, {%8,%9}, {%0,%1,%2,%3};"
        : "+f"(c[0]), "+f"(c[1]), "+f"(c[2]), "+f"(c[3])
        : "r"(a[0]), "r"(a[1]), "r"(a[2]), "r"(a[3]), "r"(b[0]), "r"(b[1]));
}
__device__ __forceinline__ void ldsm4(uint32_t* r, uint32_t addr) {
    asm volatile("ldmatrix.sync.aligned.m8n8.x4.shared.b16 {%0,%1,%2,%3}, [%4];"
        : "=r"(r[0]), "=r"(r[1]), "=r"(r[2]), "=r"(r[3]) : "r"(addr));
}
__device__ __forceinline__ unsigned short bf16u(__nv_bfloat16 h) { return *(unsigned short*)&h; }
__device__ __forceinline__ void cp16(void* dst, const void* src) {
    uint32_t s = (uint32_t)__cvta_generic_to_shared(dst);
    asm volatile("cp.async.cg.shared.global [%0], [%1], 16;" :: "r"(s), "l"(src));
}
__device__ __forceinline__ float4 ldcs4(const float4* p) {
    float4 v;
    asm volatile("ld.global.cs.v4.f32 {%0,%1,%2,%3}, [%4];"
        : "=f"(v.x), "=f"(v.y), "=f"(v.z), "=f"(v.w) : "l"(p));
    return v;
}

// ---------------- degree + normalization + bf16 hi/lo split of A (per group) ----------------
__global__ void deg_cvt_kernel(const float* __restrict__ a, int rowbase) {
    int row  = rowbase + blockIdx.x * 8 + (threadIdx.x >> 5);
    int lane = threadIdx.x & 31;
    const float4* ar4 = (const float4*)(a + (size_t)row * N_);
    __nv_bfloat16* hrow = g_Ahi + (size_t)row * N_;
    __nv_bfloat16* lrow = g_Alo + (size_t)row * N_;
    float s = 0.f;
    #pragma unroll
    for (int j = 0; j < N_/128; j++) {
        float4 v = ldcs4(&ar4[lane + j*32]);   // streaming: don't pollute L2
        s += (v.x + v.y) + (v.z + v.w);
        float f[4] = {v.x, v.y, v.z, v.w};
        uint32_t hs[4], ls[4];
        #pragma unroll
        for (int i = 0; i < 4; i++) {
            __nv_bfloat16 h = __float2bfloat16(f[i]);
            hs[i] = bf16u(h);
            ls[i] = bf16u(__float2bfloat16(f[i] - __bfloat162float(h)));
        }
        uint2 hv = make_uint2(hs[0]|(hs[1]<<16), hs[2]|(hs[3]<<16));
        uint2 lv = make_uint2(ls[0]|(ls[1]<<16), ls[2]|(ls[3]<<16));
        *(uint2*)(hrow + (size_t)(lane + j*32)*4) = hv;
        *(uint2*)(lrow + (size_t)(lane + j*32)*4) = lv;
    }
    #pragma unroll
    for (int o = 16; o; o >>= 1) s += __shfl_xor_sync(0xffffffffu, s, o);
    if (lane == 0) {
        int i = row & (N_ - 1);
        float diag = a[(size_t)row * N_ + i];
        float add  = (fabsf(diag) < 1e-7f) ? 1.0f : 0.0f;
        g_add[row] = add;
        g_dm[row]  = 1.0f / sqrtf(s + add);
    }
}

// ---------------- Y1 = dm .* (x @ W1)  (per group) ----------------
__global__ void y1_kernel(const float* __restrict__ Hin, const float* __restrict__ W,
                          float* __restrict__ Yout,
                          __nv_bfloat16* __restrict__ Thi, __nv_bfloat16* __restrict__ Tlo,
                          int rowbase) {
    const int K = F_;
    __shared__ float Ws[K*HID_];
    __shared__ float Hs[32][K];
    __shared__ float Ysm[32][33];
    int t = threadIdx.x;
    int row0 = rowbase + blockIdx.x * 32;
    for (int i = t; i < K*HID_/4; i += 256) ((float4*)Ws)[i] = ((const float4*)W)[i];
    for (int i = t; i < 32*K/4;  i += 256) ((float4*)Hs)[i] = ((const float4*)(Hin + (size_t)row0*K))[i];
    __syncthreads();
    int rb = (t >> 5) * 4, f = t & 31;
    float acc[4] = {0.f, 0.f, 0.f, 0.f};
    #pragma unroll
    for (int k = 0; k < K; k++) {
        float wv = Ws[k*HID_ + f];
        acc[0] += Hs[rb+0][k] * wv;
        acc[1] += Hs[rb+1][k] * wv;
        acc[2] += Hs[rb+2][k] * wv;
        acc[3] += Hs[rb+3][k] * wv;
    }
    #pragma unroll
    for (int j = 0; j < 4; j++) {
        int row = row0 + rb + j;
        float v = g_dm[row] * acc[j];
        Yout[(size_t)row*HID_ + f] = v;
        Ysm[rb + j][f] = v;
    }
    __syncthreads();
    int w = t >> 5, lane = t & 31;
    int bb = row0 >> 11, n0 = row0 & (N_ - 1);
    #pragma unroll
    for (int jj = 0; jj < 4; jj++) {
        int ff = w*4 + jj;
        float v = Ysm[lane][ff];
        __nv_bfloat16 h = __float2bfloat16(v);
        size_t ti = ((size_t)bb*HID_ + ff)*N_ + n0 + lane;
        Thi[ti] = h;
        Tlo[ti] = __float2bfloat16(v - __bfloat162float(h));
    }
}

// ---------------- HMMA GEMM (BM=64, 2 CTAs/SM) + fused epilogue ----------------
#define BM 64
#define BK 64
#define NT (N_/BK)
#define NSTAGE 4
#define AHI_OFF 0
#define ALO_OFF 8192
#define BHI_OFF 16384
#define BLO_OFF 20480
#define STGSZ   24576
#define WSM_OFF (NSTAGE*STGSZ)
#define GEMM_SMEM (WSM_OFF + 4096)

__device__ __forceinline__ void fill_async(char* stage, int t, int b, int row0, int k0,
                                           const __nv_bfloat16* BThi, const __nv_bfloat16* BTli) {
    const __nv_bfloat16* Ah = g_Ahi + ((size_t)(b*N_ + row0))*N_ + k0;
    const __nv_bfloat16* Al = g_Alo + ((size_t)(b*N_ + row0))*N_ + k0;
    const __nv_bfloat16* Bh = BThi + (size_t)b*HID_*N_ + k0;
    const __nv_bfloat16* Bl = BTli + (size_t)b*HID_*N_ + k0;
    #pragma unroll
    for (int i = 0; i < 2; i++) {
        int c = t + i*256;
        int r = c >> 3, seg = c & 7;
        int x = (seg*16) ^ ((r & 7) << 4);
        cp16(stage + AHI_OFF + r*128 + x, Ah + (size_t)r*N_ + seg*8);
        cp16(stage + ALO_OFF + r*128 + x, Al + (size_t)r*N_ + seg*8);
    }
    {
        int r = t >> 3, seg = t & 7;
        int x = (seg*16) ^ ((r & 7) << 4);
        cp16(stage + BHI_OFF + r*128 + x, Bh + (size_t)r*N_ + k0*0 + seg*8);
        cp16(stage + BLO_OFF + r*128 + x, Bl + (size_t)r*N_ + k0*0 + seg*8);
    }
}

__global__ void __launch_bounds__(256, 2) gemm_kernel(
    const __nv_bfloat16* __restrict__ BThi, const __nv_bfloat16* __restrict__ BTli,
    const float* __restrict__ Yin, const float* __restrict__ bias,
    const float* __restrict__ Wnext,
    float* __restrict__ Yout,
    __nv_bfloat16* __restrict__ Thi_out, __nv_bfloat16* __restrict__ Tlo_out,
    int b0) {
    extern __shared__ char sm[];
    int t = threadIdx.x;
    int lane = t & 31, w = t >> 5;
    int wm = w & 3, wn = w >> 2;
    int g = lane >> 2, t4 = lane & 3;
    int b = blockIdx.y + b0, row0 = blockIdx.x * BM;

    float* wsm = (float*)(sm + WSM_OFF);
    if (Wnext) for (int i = t; i < HID_*HID_; i += 256) wsm[i] = Wnext[i];

    int row_in = lane & 15;
    int half = lane >> 4;
    int swz = (row_in & 7) << 4;
    uint32_t smb = (uint32_t)__cvta_generic_to_shared(sm);
    uint32_t aoff = (wm*16 + row_in) * 128;
    uint32_t boff = (wn*16 + row_in) * 128;

    float acc[2][4];
    #pragma unroll
    for (int nt = 0; nt < 2; nt++)
        #pragma unroll
        for (int i = 0; i < 4; i++) acc[nt][i] = 0.f;

    #pragma unroll
    for (int p = 0; p < NSTAGE-1; p++) {
        fill_async(sm + p*STGSZ, t, b, row0, p*BK, BThi, BTli);
        asm volatile("cp.async.commit_group;" ::: "memory");
    }

    for (int kt = 0; kt < NT; kt++) {
        asm volatile("cp.async.wait_group %0;" :: "n"(NSTAGE-2) : "memory");
        __syncthreads();
        if (kt + NSTAGE - 1 < NT)
            fill_async(sm + ((kt + NSTAGE - 1) % NSTAGE)*STGSZ, t, b, row0, (kt + NSTAGE - 1)*BK, BThi, BTli);
        asm volatile("cp.async.commit_group;" ::: "memory");

        uint32_t stg = smb + (kt % NSTAGE)*STGSZ;
        #pragma unroll
        for (int kk = 0; kk < 4; kk++) {
            uint32_t koff = (uint32_t)((kk*32 + half*16) ^ swz);
            uint32_t ah[4], al[4], bh[4], bl[4];
            ldsm4(ah, stg + AHI_OFF + aoff + koff);
            ldsm4(al, stg + ALO_OFF + aoff + koff);
            ldsm4(bh, stg + BHI_OFF + boff + koff);
            ldsm4(bl, stg + BLO_OFF + boff + koff);
            uint32_t bh0[2] = {bh[0], bh[2]}, bh1[2] = {bh[1], bh[3]};
            uint32_t bl0[2] = {bl[0], bl[2]}, bl1[2] = {bl[1], bl[3]};
            mma16816(acc[0], ah, bh0);
            mma16816(acc[0], ah, bl0);
            mma16816(acc[0], al, bh0);
            mma16816(acc[1], ah, bh1);
            mma16816(acc[1], ah, bl1);
            mma16816(acc[1], al, bh1);
        }
    }

    // ---- epilogue ----
    __syncthreads();
    float* Hs = (float*)sm;                    // [64][34] fp32 (reuses stage smem)
    const float* Yg = Yin + (size_t)b*N_*HID_;

    if (Wnext) {
        int rL = wm*16 + g;
        int rH = rL + 8;
        int rowL = row0 + rL, rowH = row0 + rH;
        float dmL = g_dm[b*N_ + rowL], adL = g_add[b*N_ + rowL];
        float dmH = g_dm[b*N_ + rowH], adH = g_add[b*N_ + rowH];
        #pragma unroll
        for (int nt = 0; nt < 2; nt++) {
            int col = wn*16 + nt*8 + 2*t4;
            float2 bs = *(const float2*)&bias[col];
            float2 yL = *(const float2*)&Yg[(size_t)rowL*HID_ + col];
            float2 yH = *(const float2*)&Yg[(size_t)rowH*HID_ + col];
            Hs[rL*34 + col]     = fmaxf(fmaf(dmL, acc[nt][0] + adL*yL.x, bs.x), 0.f);
            Hs[rL*34 + col + 1] = fmaxf(fmaf(dmL, acc[nt][1] + adL*yL.y, bs.y), 0.f);
            Hs[rH*34 + col]     = fmaxf(fmaf(dmH, acc[nt][2] + adH*yH.x, bs.x), 0.f);
            Hs[rH*34 + col + 1] = fmaxf(fmaf(dmH, acc[nt][3] + adH*yH.y, bs.y), 0.f);
        }
        __syncthreads();
        int f = t & 31, rb = (t >> 5) * 8;
        float acc2[8];
        #pragma unroll
        for (int r = 0; r < 8; r++) acc2[r] = 0.f;
        #pragma unroll
        for (int k = 0; k < HID_; k++) {
            float wv = wsm[k*HID_ + f];
            #pragma unroll
            for (int r = 0; r < 8; r++) acc2[r] += Hs[(rb + r)*34 + k] * wv;
        }
        int n0g = b*N_ + row0 + rb;
        uint32_t hp[4], lp[4];
        unsigned short hh[8], ll[8];
        #pragma unroll
        for (int r = 0; r < 8; r++) {
            float v = g_dm[n0g + r] * acc2[r];
            Yout[(size_t)(n0g + r)*HID_ + f] = v;
            __nv_bfloat16 hb = __float2bfloat16(v);
            hh[r] = bf16u(hb);
            ll[r] = bf16u(__float2bfloat16(v - __bfloat162float(hb)));
        }
        #pragma unroll
        for (int j = 0; j < 4; j++) {
            hp[j] = (uint32_t)hh[2*j] | ((uint32_t)hh[2*j+1] << 16);
            lp[j] = (uint32_t)ll[2*j] | ((uint32_t)ll[2*j+1] << 16);
        }
        size_t to = ((size_t)b*HID_ + f)*N_ + row0 + rb;
        *(uint4*)(Thi_out + to) = *(uint4*)&hp[0];
        *(uint4*)(Tlo_out + to) = *(uint4*)&lp[0];
    } else {
        int rowL = row0 + wm*16 + g;
        int rowH = rowL + 8;
        float dmL = g_dm[b*N_ + rowL], adL = g_add[b*N_ + rowL];
        float dmH = g_dm[b*N_ + rowH], adH = g_add[b*N_ + rowH];
        #pragma unroll
        for (int nt = 0; nt < 2; nt++) {
            int col = wn*16 + nt*8 + 2*t4;
            float2 bs = *(const float2*)&bias[col];
            float2 yL = *(const float2*)&Yg[(size_t)rowL*HID_ + col];
            float2 yH = *(const float2*)&Yg[(size_t)rowH*HID_ + col];
            float m0 = fmaxf(fmaf(dmL, acc[nt][0] + adL*yL.x, bs.x),
                             fmaf(dmH, acc[nt][2] + adH*yH.x, bs.x));
            float m1 = fmaxf(fmaf(dmL, acc[nt][1] + adL*yL.y, bs.y),
                             fmaf(dmH, acc[nt][3] + adH*yH.y, bs.y));
            atomicMax((int*)&g_pool[b*HID_ + col],     __float_as_int(fmaxf(m0, 0.f)));
            atomicMax((int*)&g_pool[b*HID_ + col + 1], __float_as_int(fmaxf(m1, 0.f)));
        }
    }
}

// ---------------- MLP head ----------------
__global__ void head_kernel(const float* __restrict__ Wf1, const float* __restrict__ bf1,
                            const float* __restrict__ Wf2, const float* __restrict__ bf2,
                            float* __restrict__ out) {
    int w = threadIdx.x >> 5, lane = threadIdx.x & 31;
    float o = 0.f;
    #pragma unroll
    for (int ii = 0; ii < 2; ii++) {
        int j = lane + 32*ii;
        float s = bf1[j];
        #pragma unroll
        for (int f = 0; f < HID_; f++) s += g_pool[w*HID_ + f] * Wf1[f*2*HID_ + j];
        o += fmaxf(s, 0.f) * Wf2[j];
    }
    #pragma unroll
    for (int off = 16; off; off >>= 1) o += __shfl_xor_sync(0xffffffffu, o, off);
    if (lane == 0) out[w] = o + bf2[0];
}

// ---------------- launch ----------------
extern "C" void kernel_launch(void* const* d_in, const int* in_sizes, int n_in,
                              void* d_out, int out_size) {
    const float* x   = (const float*)d_in[0];
    const float* a   = (const float*)d_in[1];
    const float* W1  = (const float*)d_in[2];
    const float* b1  = (const float*)d_in[3];
    const float* W2  = (const float*)d_in[4];
    const float* b2  = (const float*)d_in[5];
    const float* W3  = (const float*)d_in[6];
    const float* b3  = (const float*)d_in[7];
    const float* Wf1 = (const float*)d_in[8];
    const float* bf1 = (const float*)d_in[9];
    const float* Wf2 = (const float*)d_in[10];
    const float* bf2 = (const float*)d_in[11];
    float* out = (float*)d_out;

    cudaFuncSetAttribute(gemm_kernel, cudaFuncAttributeMaxDynamicSharedMemorySize, GEMM_SMEM);

    float *Ya, *Yb;  __nv_bfloat16 *Tha, *Tla, *Thb, *Tlb;
    cudaGetSymbolAddress((void**)&Ya,  g_Ya);
    cudaGetSymbolAddress((void**)&Yb,  g_Yb);
    cudaGetSymbolAddress((void**)&Tha, g_Thi_a);
    cudaGetSymbolAddress((void**)&Tla, g_Tlo_a);
    cudaGetSymbolAddress((void**)&Thb, g_Thi_b);
    cudaGetSymbolAddress((void**)&Tlb, g_Tlo_b);

    dim3 gg(N_/BM, GRP);

    for (int grp = 0; grp < B_/GRP; grp++) {
        int b0 = grp * GRP;
        int rowbase = b0 * N_;
        deg_cvt_kernel<<<GRP*N_/8, 256>>>(a, rowbase);
        y1_kernel<<<GRP*N_/32, 256>>>(x, W1, Ya, Tha, Tla, rowbase);
        gemm_kernel<<<gg, 256, GEMM_SMEM>>>(Tha, Tla, Ya, b1, W2, Yb, Thb, Tlb, b0);
        gemm_kernel<<<gg, 256, GEMM_SMEM>>>(Thb, Tlb, Yb, b2, W3, Ya, Tha, Tla, b0);
        gemm_kernel<<<gg, 256, GEMM_SMEM>>>(Tha, Tla, Ya, b3, nullptr, nullptr, nullptr, nullptr, b0);
    }
    head_kernel<<<1, 256>>>(Wf1, bf1, Wf2, bf2, out);
}

// round 12
// speedup vs baseline: 1.3052x; 1.3052x over previous
#include <cuda_runtime.h>
#include <cuda_bf16.h>
#include <cstdint>

#define B_ 8
#define N_ 2048
#define F_ 64
#define HID_ 32
#define BN_TOTAL (B_*N_)

// ---------------- scratch ----------------
__device__ float g_dm[BN_TOTAL];
__device__ float g_add[BN_TOTAL];
__device__ float g_Ya[BN_TOTAL*HID_];                // fp32 Y ping
__device__ float g_Yb[BN_TOTAL*HID_];                // fp32 Y pong
__device__ float g_pool[B_*HID_];                    // global max pool (relu>=0, int-ordered)
__device__ __nv_bfloat16 g_Thi_a[B_*HID_*N_];        // Y^T bf16 hi ping  [b][f][n]
__device__ __nv_bfloat16 g_Tlo_a[B_*HID_*N_];
__device__ __nv_bfloat16 g_Thi_b[B_*HID_*N_];        // pong
__device__ __nv_bfloat16 g_Tlo_b[B_*HID_*N_];

// ---------------- helpers ----------------
__device__ __forceinline__ void mma16816(float* c, const uint32_t* a, const uint32_t* b) {
    asm volatile("mma.sync.aligned.m16n8k16.row.col.f32.bf16.bf16.f32 "
        "{%0,%1,%2,%3}, {%4,%5,%6,%7}, {%8,%9}, {%0,%1,%2,%3};"
        : "+f"(c[0]), "+f"(c[1]), "+f"(c[2]), "+f"(c[3])
        : "r"(a[0]), "r"(a[1]), "r"(a[2]), "r"(a[3]), "r"(b[0]), "r"(b[1]));
}
__device__ __forceinline__ void ldsm4(uint32_t* r, uint32_t addr) {
    asm volatile("ldmatrix.sync.aligned.m8n8.x4.shared.b16 {%0,%1,%2,%3}, [%4];"
        : "=r"(r[0]), "=r"(r[1]), "=r"(r[2]), "=r"(r[3]) : "r"(addr));
}
__device__ __forceinline__ unsigned short bf16u(__nv_bfloat16 h) { return *(unsigned short*)&h; }
__device__ __forceinline__ void cp16(void* dst, const void* src) {
    uint32_t s = (uint32_t)__cvta_generic_to_shared(dst);
    asm volatile("cp.async.cg.shared.global [%0], [%1], 16;" :: "r"(s), "l"(src));
}
__device__ __forceinline__ float4 ldcs4(const float4* p) {
    float4 v;
    asm volatile("ld.global.cs.v4.f32 {%0,%1,%2,%3}, [%4];"
        : "=f"(v.x), "=f"(v.y), "=f"(v.z), "=f"(v.w) : "l"(p));
    return v;
}
// split a float2 into packed bf16 hi + bf16 lo pairs (same numerics as __float2bfloat16 path)
__device__ __forceinline__ void cvt_pair(float2 f, uint32_t& hi, uint32_t& lo) {
    asm("cvt.rn.bf16x2.f32 %0, %1, %2;" : "=r"(hi) : "f"(f.y), "f"(f.x));
    float h0 = __uint_as_float(hi << 16);
    float h1 = __uint_as_float(hi & 0xffff0000u);
    float l0 = f.x - h0, l1 = f.y - h1;
    asm("cvt.rn.bf16x2.f32 %0, %1, %2;" : "=r"(lo) : "f"(l1), "f"(l0));
}

// ---------------- degree + normalization only ----------------
__global__ void deg_kernel(const float* __restrict__ a) {
    int row  = blockIdx.x * 8 + (threadIdx.x >> 5);
    int lane = threadIdx.x & 31;
    const float4* ar4 = (const float4*)(a + (size_t)row * N_);
    float s = 0.f;
    #pragma unroll
    for (int j = 0; j < N_/128; j++) {
        float4 v = ldcs4(&ar4[lane + j*32]);
        s += (v.x + v.y) + (v.z + v.w);
    }
    #pragma unroll
    for (int o = 16; o; o >>= 1) s += __shfl_xor_sync(0xffffffffu, s, o);
    if (lane == 0) {
        int i = row & (N_ - 1);
        float diag = a[(size_t)row * N_ + i];
        float add  = (fabsf(diag) < 1e-7f) ? 1.0f : 0.0f;
        g_add[row] = add;
        g_dm[row]  = 1.0f / sqrtf(s + add);
    }
}

// ---------------- Y1 = dm .* (x @ W1) ----------------
__global__ void y1_kernel(const float* __restrict__ Hin, const float* __restrict__ W,
                          float* __restrict__ Yout,
                          __nv_bfloat16* __restrict__ Thi, __nv_bfloat16* __restrict__ Tlo) {
    const int K = F_;
    __shared__ float Ws[K*HID_];
    __shared__ float Hs[32][K];
    __shared__ float Ysm[32][33];
    int t = threadIdx.x;
    int row0 = blockIdx.x * 32;
    for (int i = t; i < K*HID_/4; i += 256) ((float4*)Ws)[i] = ((const float4*)W)[i];
    for (int i = t; i < 32*K/4;  i += 256) ((float4*)Hs)[i] = ((const float4*)(Hin + (size_t)row0*K))[i];
    __syncthreads();
    int rb = (t >> 5) * 4, f = t & 31;
    float acc[4] = {0.f, 0.f, 0.f, 0.f};
    #pragma unroll
    for (int k = 0; k < K; k++) {
        float wv = Ws[k*HID_ + f];
        acc[0] += Hs[rb+0][k] * wv;
        acc[1] += Hs[rb+1][k] * wv;
        acc[2] += Hs[rb+2][k] * wv;
        acc[3] += Hs[rb+3][k] * wv;
    }
    #pragma unroll
    for (int j = 0; j < 4; j++) {
        int row = row0 + rb + j;
        float v = g_dm[row] * acc[j];
        Yout[(size_t)row*HID_ + f] = v;
        Ysm[rb + j][f] = v;
    }
    __syncthreads();
    int w = t >> 5, lane = t & 31;
    int bb = row0 >> 11, n0 = row0 & (N_ - 1);
    #pragma unroll
    for (int jj = 0; jj < 4; jj++) {
        int ff = w*4 + jj;
        float v = Ysm[lane][ff];
        __nv_bfloat16 h = __float2bfloat16(v);
        size_t ti = ((size_t)bb*HID_ + ff)*N_ + n0 + lane;
        Thi[ti] = h;
        Tlo[ti] = __float2bfloat16(v - __bfloat162float(h));
    }
}

// ---------------- HMMA GEMM: fp32 A stream, register-path split, fused epilogue ----------------
#define BM 64
#define BK 64
#define NT (N_/BK)
#define NSTAGE 4
// per-stage: A fp32 (64 rows x 256B = 16K) | BHI 4K | BLO 4K
#define AFP_OFF 0
#define BHI_OFF 16384
#define BLO_OFF 20480
#define STGSZ   24576
#define WSM_OFF (NSTAGE*STGSZ)
#define GEMM_SMEM (WSM_OFF + 4096)            // 100 KB -> 2 CTAs/SM

__device__ __forceinline__ void fill_async(char* stage, int t, const float* Afp,
                                           const __nv_bfloat16* Bh, const __nv_bfloat16* Bl,
                                           int k0) {
    // A fp32: 64 rows x 16 chunks of 16B = 1024 chunks / 256 thr = 4 each
    #pragma unroll
    for (int i = 0; i < 4; i++) {
        int c = t + i*256;
        int r = c >> 4, ch = c & 15;
        int x = (ch*16) ^ ((r & 7) << 4);
        cp16(stage + AFP_OFF + r*256 + x, Afp + (size_t)r*N_ + k0 + ch*4);
    }
    // B: 32 rows x 8 chunks of 16B, hi and lo
    {
        int r = t >> 3, seg = t & 7;
        int x = (seg*16) ^ ((r & 7) << 4);
        cp16(stage + BHI_OFF + r*128 + x, Bh + (size_t)r*N_ + k0 + seg*8);
        cp16(stage + BLO_OFF + r*128 + x, Bl + (size_t)r*N_ + k0 + seg*8);
    }
}

__global__ void __launch_bounds__(256, 2) gemm_kernel(
    const float* __restrict__ A,
    const __nv_bfloat16* __restrict__ BThi, const __nv_bfloat16* __restrict__ BTli,
    const float* __restrict__ Yin, const float* __restrict__ bias,
    const float* __restrict__ Wnext,
    float* __restrict__ Yout,
    __nv_bfloat16* __restrict__ Thi_out, __nv_bfloat16* __restrict__ Tlo_out) {
    extern __shared__ char sm[];
    int t = threadIdx.x;
    int lane = t & 31, w = t >> 5;
    int wm = w & 3, wn = w >> 2;               // warp tile: rows wm*16..+15, cols wn*16..+15
    int g = lane >> 2, t4 = lane & 3;
    int b = blockIdx.y, row0 = blockIdx.x * BM;

    const float* Afp = A + (size_t)b*N_*N_ + (size_t)row0*N_;
    const __nv_bfloat16* Bh = BThi + (size_t)b*HID_*N_;
    const __nv_bfloat16* Bl = BTli + (size_t)b*HID_*N_;

    float* wsm = (float*)(sm + WSM_OFF);
    if (Wnext) for (int i = t; i < HID_*HID_; i += 256) wsm[i] = Wnext[i];

    // B ldmatrix addressing
    int row_in = lane & 15;
    int half = lane >> 4;
    int swz = (row_in & 7) << 4;
    uint32_t smb = (uint32_t)__cvta_generic_to_shared(sm);
    uint32_t boff = (wn*16 + row_in) * 128;

    // A fp32 fragment addressing: rows wm*16+g and +8, float2 at k = kk*16 + 2*t4 (+8)
    int rowA0 = wm*16 + g;
    uint32_t abase0 = rowA0 * 256;             // row stride 256B
    uint32_t abase1 = (rowA0 + 8) * 256;
    uint32_t asw = (uint32_t)(g << 4);         // (row&7)<<4, same for both rows
    uint32_t acol = (uint32_t)(8 * t4);        // byte offset of float2 within 64B k-group

    float acc[2][4];
    #pragma unroll
    for (int nt = 0; nt < 2; nt++)
        #pragma unroll
        for (int i = 0; i < 4; i++) acc[nt][i] = 0.f;

    #pragma unroll
    for (int p = 0; p < NSTAGE-1; p++) {
        fill_async(sm + p*STGSZ, t, Afp, Bh, Bl, p*BK);
        asm volatile("cp.async.commit_group;" ::: "memory");
    }

    for (int kt = 0; kt < NT; kt++) {
        asm volatile("cp.async.wait_group %0;" :: "n"(NSTAGE-2) : "memory");
        __syncthreads();
        if (kt + NSTAGE - 1 < NT)
            fill_async(sm + ((kt + NSTAGE - 1) % NSTAGE)*STGSZ, t, Afp, Bh, Bl, (kt + NSTAGE - 1)*BK);
        asm volatile("cp.async.commit_group;" ::: "memory");

        uint32_t stg = smb + (kt % NSTAGE)*STGSZ;
        char* stgc = sm + (kt % NSTAGE)*STGSZ;
        #pragma unroll
        for (int kk = 0; kk < 4; kk++) {
            // ---- A: load fp32 fragment elements, split to bf16 hi/lo in regs ----
            uint32_t c0 = (uint32_t)(kk*64) + acol;        // k byte offset (first 8-col half)
            uint32_t c1 = c0 + 32;                         // +8 k elements
            float2 fa0 = *(float2*)(stgc + AFP_OFF + abase0 + (c0 ^ asw));
            float2 fa1 = *(float2*)(stgc + AFP_OFF + abase1 + (c0 ^ asw));
            float2 fa2 = *(float2*)(stgc + AFP_OFF + abase0 + (c1 ^ asw));
            float2 fa3 = *(float2*)(stgc + AFP_OFF + abase1 + (c1 ^ asw));
            uint32_t ah[4], al[4];
            cvt_pair(fa0, ah[0], al[0]);
            cvt_pair(fa1, ah[1], al[1]);
            cvt_pair(fa2, ah[2], al[2]);
            cvt_pair(fa3, ah[3], al[3]);
            // ---- B: ldmatrix ----
            uint32_t koff = (uint32_t)((kk*32 + half*16) ^ swz);
            uint32_t bh4[4], bl4[4];
            ldsm4(bh4, stg + BHI_OFF + boff + koff);
            ldsm4(bl4, stg + BLO_OFF + boff + koff);
            uint32_t bh0[2] = {bh4[0], bh4[2]}, bh1[2] = {bh4[1], bh4[3]};
            uint32_t bl0[2] = {bl4[0], bl4[2]}, bl1[2] = {bl4[1], bl4[3]};
            mma16816(acc[0], ah, bh0);
            mma16816(acc[0], ah, bl0);
            mma16816(acc[0], al, bh0);
            mma16816(acc[1], ah, bh1);
            mma16816(acc[1], ah, bl1);
            mma16816(acc[1], al, bh1);
        }
    }

    // ---- epilogue ----
    __syncthreads();
    float* Hs = (float*)sm;                    // [64][34] fp32 (reuses stage smem)
    const float* Yg = Yin + (size_t)b*N_*HID_;

    if (Wnext) {
        int rL = wm*16 + g;
        int rH = rL + 8;
        int rowL = row0 + rL, rowH = row0 + rH;
        float dmL = g_dm[b*N_ + rowL], adL = g_add[b*N_ + rowL];
        float dmH = g_dm[b*N_ + rowH], adH = g_add[b*N_ + rowH];
        #pragma unroll
        for (int nt = 0; nt < 2; nt++) {
            int col = wn*16 + nt*8 + 2*t4;
            float2 bs = *(const float2*)&bias[col];
            float2 yL = *(const float2*)&Yg[(size_t)rowL*HID_ + col];
            float2 yH = *(const float2*)&Yg[(size_t)rowH*HID_ + col];
            Hs[rL*34 + col]     = fmaxf(fmaf(dmL, acc[nt][0] + adL*yL.x, bs.x), 0.f);
            Hs[rL*34 + col + 1] = fmaxf(fmaf(dmL, acc[nt][1] + adL*yL.y, bs.y), 0.f);
            Hs[rH*34 + col]     = fmaxf(fmaf(dmH, acc[nt][2] + adH*yH.x, bs.x), 0.f);
            Hs[rH*34 + col + 1] = fmaxf(fmaf(dmH, acc[nt][3] + adH*yH.y, bs.y), 0.f);
        }
        __syncthreads();
        int f = t & 31, rb = (t >> 5) * 8;
        float acc2[8];
        #pragma unroll
        for (int r = 0; r < 8; r++) acc2[r] = 0.f;
        #pragma unroll
        for (int k = 0; k < HID_; k++) {
            float wv = wsm[k*HID_ + f];
            #pragma unroll
            for (int r = 0; r < 8; r++) acc2[r] += Hs[(rb + r)*34 + k] * wv;
        }
        int n0g = b*N_ + row0 + rb;
        uint32_t hp[4], lp[4];
        unsigned short hh[8], ll[8];
        #pragma unroll
        for (int r = 0; r < 8; r++) {
            float v = g_dm[n0g + r] * acc2[r];
            Yout[(size_t)(n0g + r)*HID_ + f] = v;
            __nv_bfloat16 hb = __float2bfloat16(v);
            hh[r] = bf16u(hb);
            ll[r] = bf16u(__float2bfloat16(v - __bfloat162float(hb)));
        }
        #pragma unroll
        for (int j = 0; j < 4; j++) {
            hp[j] = (uint32_t)hh[2*j] | ((uint32_t)hh[2*j+1] << 16);
            lp[j] = (uint32_t)ll[2*j] | ((uint32_t)ll[2*j+1] << 16);
        }
        size_t to = ((size_t)b*HID_ + f)*N_ + row0 + rb;
        *(uint4*)(Thi_out + to) = *(uint4*)&hp[0];
        *(uint4*)(Tlo_out + to) = *(uint4*)&lp[0];
    } else {
        int rowL = row0 + wm*16 + g;
        int rowH = rowL + 8;
        float dmL = g_dm[b*N_ + rowL], adL = g_add[b*N_ + rowL];
        float dmH = g_dm[b*N_ + rowH], adH = g_add[b*N_ + rowH];
        #pragma unroll
        for (int nt = 0; nt < 2; nt++) {
            int col = wn*16 + nt*8 + 2*t4;
            float2 bs = *(const float2*)&bias[col];
            float2 yL = *(const float2*)&Yg[(size_t)rowL*HID_ + col];
            float2 yH = *(const float2*)&Yg[(size_t)rowH*HID_ + col];
            float m0 = fmaxf(fmaf(dmL, acc[nt][0] + adL*yL.x, bs.x),
                             fmaf(dmH, acc[nt][2] + adH*yH.x, bs.x));
            float m1 = fmaxf(fmaf(dmL, acc[nt][1] + adL*yL.y, bs.y),
                             fmaf(dmH, acc[nt][3] + adH*yH.y, bs.y));
            atomicMax((int*)&g_pool[b*HID_ + col],     __float_as_int(fmaxf(m0, 0.f)));
            atomicMax((int*)&g_pool[b*HID_ + col + 1], __float_as_int(fmaxf(m1, 0.f)));
        }
    }
}

// ---------------- MLP head ----------------
__global__ void head_kernel(const float* __restrict__ Wf1, const float* __restrict__ bf1,
                            const float* __restrict__ Wf2, const float* __restrict__ bf2,
                            float* __restrict__ out) {
    int w = threadIdx.x >> 5, lane = threadIdx.x & 31;
    float o = 0.f;
    #pragma unroll
    for (int ii = 0; ii < 2; ii++) {
        int j = lane + 32*ii;
        float s = bf1[j];
        #pragma unroll
        for (int f = 0; f < HID_; f++) s += g_pool[w*HID_ + f] * Wf1[f*2*HID_ + j];
        o += fmaxf(s, 0.f) * Wf2[j];
    }
    #pragma unroll
    for (int off = 16; off; off >>= 1) o += __shfl_xor_sync(0xffffffffu, o, off);
    if (lane == 0) out[w] = o + bf2[0];
}

// ---------------- launch ----------------
extern "C" void kernel_launch(void* const* d_in, const int* in_sizes, int n_in,
                              void* d_out, int out_size) {
    const float* x   = (const float*)d_in[0];
    const float* a   = (const float*)d_in[1];
    const float* W1  = (const float*)d_in[2];
    const float* b1  = (const float*)d_in[3];
    const float* W2  = (const float*)d_in[4];
    const float* b2  = (const float*)d_in[5];
    const float* W3  = (const float*)d_in[6];
    const float* b3  = (const float*)d_in[7];
    const float* Wf1 = (const float*)d_in[8];
    const float* bf1 = (const float*)d_in[9];
    const float* Wf2 = (const float*)d_in[10];
    const float* bf2 = (const float*)d_in[11];
    float* out = (float*)d_out;

    cudaFuncSetAttribute(gemm_kernel, cudaFuncAttributeMaxDynamicSharedMemorySize, GEMM_SMEM);

    float *Ya, *Yb;  __nv_bfloat16 *Tha, *Tla, *Thb, *Tlb;
    cudaGetSymbolAddress((void**)&Ya,  g_Ya);
    cudaGetSymbolAddress((void**)&Yb,  g_Yb);
    cudaGetSymbolAddress((void**)&Tha, g_Thi_a);
    cudaGetSymbolAddress((void**)&Tla, g_Tlo_a);
    cudaGetSymbolAddress((void**)&Thb, g_Thi_b);
    cudaGetSymbolAddress((void**)&Tlb, g_Tlo_b);

    dim3 gg(N_/BM, B_);

    deg_kernel<<<BN_TOTAL/8, 256>>>(a);
    y1_kernel<<<BN_TOTAL/32, 256>>>(x, W1, Ya, Tha, Tla);
    gemm_kernel<<<gg, 256, GEMM_SMEM>>>(a, Tha, Tla, Ya, b1, W2, Yb, Thb, Tlb);
    gemm_kernel<<<gg, 256, GEMM_SMEM>>>(a, Thb, Tlb, Yb, b2, W3, Ya, Tha, Tla);
    gemm_kernel<<<gg, 256, GEMM_SMEM>>>(a, Tha, Tla, Ya, b3, nullptr, nullptr, nullptr, nullptr);
    head_kernel<<<1, 256>>>(Wf1, bf1, Wf2, bf2, out);
}

// round 13
// speedup vs baseline: 1.4811x; 1.1348x over previous
#include <cuda_runtime.h>
#include <cuda_bf16.h>
#include <cstdint>

#define B_ 8
#define N_ 2048
#define F_ 64
#define HID_ 32
#define BN_TOTAL (B_*N_)

// ---------------- scratch ----------------
__device__ float g_dm[BN_TOTAL];
__device__ float g_add[BN_TOTAL];
__device__ float g_Ya[BN_TOTAL*HID_];
__device__ float g_Yb[BN_TOTAL*HID_];
__device__ float g_pool[B_*HID_];
__device__ __nv_bfloat16 g_Thi_a[B_*HID_*N_];
__device__ __nv_bfloat16 g_Tlo_a[B_*HID_*N_];
__device__ __nv_bfloat16 g_Thi_b[B_*HID_*N_];
__device__ __nv_bfloat16 g_Tlo_b[B_*HID_*N_];

// ---------------- helpers ----------------
__device__ __forceinline__ void mma16816(float* c, const uint32_t* a, const uint32_t* b) {
    asm volatile("mma.sync.aligned.m16n8k16.row.col.f32.bf16.bf16.f32 "
        "{%0,%1,%2,%3}, {%4,%5,%6,%7}, {%8,%9}, {%0,%1,%2,%3};"
        : "+f"(c[0]), "+f"(c[1]), "+f"(c[2]), "+f"(c[3])
        : "r"(a[0]), "r"(a[1]), "r"(a[2]), "r"(a[3]), "r"(b[0]), "r"(b[1]));
}
__device__ __forceinline__ void ldsm4(uint32_t* r, uint32_t addr) {
    asm volatile("ldmatrix.sync.aligned.m8n8.x4.shared.b16 {%0,%1,%2,%3}, [%4];"
        : "=r"(r[0]), "=r"(r[1]), "=r"(r[2]), "=r"(r[3]) : "r"(addr));
}
__device__ __forceinline__ unsigned short bf16u(__nv_bfloat16 h) { return *(unsigned short*)&h; }
__device__ __forceinline__ void cp16(void* dst, const void* src) {
    uint32_t s = (uint32_t)__cvta_generic_to_shared(dst);
    asm volatile("cp.async.cg.shared.global [%0], [%1], 16;" :: "r"(s), "l"(src));
}
__device__ __forceinline__ float4 ldcs4(const float4* p) {
    float4 v;
    asm volatile("ld.global.cs.v4.f32 {%0,%1,%2,%3}, [%4];"
        : "=f"(v.x), "=f"(v.y), "=f"(v.z), "=f"(v.w) : "l"(p));
    return v;
}
__device__ __forceinline__ void cvt_pair(float2 f, uint32_t& hi, uint32_t& lo) {
    asm("cvt.rn.bf16x2.f32 %0, %1, %2;" : "=r"(hi) : "f"(f.y), "f"(f.x));
    float h0 = __uint_as_float(hi << 16);
    float h1 = __uint_as_float(hi & 0xffff0000u);
    float l0 = f.x - h0, l1 = f.y - h1;
    asm("cvt.rn.bf16x2.f32 %0, %1, %2;" : "=r"(lo) : "f"(l1), "f"(l0));
}

// ---------------- degree + normalization only ----------------
__global__ void deg_kernel(const float* __restrict__ a) {
    int row  = blockIdx.x * 8 + (threadIdx.x >> 5);
    int lane = threadIdx.x & 31;
    const float4* ar4 = (const float4*)(a + (size_t)row * N_);
    float s = 0.f;
    #pragma unroll
    for (int j = 0; j < N_/128; j++) {
        float4 v = ldcs4(&ar4[lane + j*32]);
        s += (v.x + v.y) + (v.z + v.w);
    }
    #pragma unroll
    for (int o = 16; o; o >>= 1) s += __shfl_xor_sync(0xffffffffu, s, o);
    if (lane == 0) {
        int i = row & (N_ - 1);
        float diag = a[(size_t)row * N_ + i];
        float add  = (fabsf(diag) < 1e-7f) ? 1.0f : 0.0f;
        g_add[row] = add;
        g_dm[row]  = 1.0f / sqrtf(s + add);
    }
}

// ---------------- Y1 = dm .* (x @ W1) ----------------
__global__ void y1_kernel(const float* __restrict__ Hin, const float* __restrict__ W,
                          float* __restrict__ Yout,
                          __nv_bfloat16* __restrict__ Thi, __nv_bfloat16* __restrict__ Tlo) {
    const int K = F_;
    __shared__ float Ws[K*HID_];
    __shared__ float Hs[32][K];
    __shared__ float Ysm[32][33];
    int t = threadIdx.x;
    int row0 = blockIdx.x * 32;
    for (int i = t; i < K*HID_/4; i += 256) ((float4*)Ws)[i] = ((const float4*)W)[i];
    for (int i = t; i < 32*K/4;  i += 256) ((float4*)Hs)[i] = ((const float4*)(Hin + (size_t)row0*K))[i];
    __syncthreads();
    int rb = (t >> 5) * 4, f = t & 31;
    float acc[4] = {0.f, 0.f, 0.f, 0.f};
    #pragma unroll
    for (int k = 0; k < K; k++) {
        float wv = Ws[k*HID_ + f];
        acc[0] += Hs[rb+0][k] * wv;
        acc[1] += Hs[rb+1][k] * wv;
        acc[2] += Hs[rb+2][k] * wv;
        acc[3] += Hs[rb+3][k] * wv;
    }
    #pragma unroll
    for (int j = 0; j < 4; j++) {
        int row = row0 + rb + j;
        float v = g_dm[row] * acc[j];
        Yout[(size_t)row*HID_ + f] = v;
        Ysm[rb + j][f] = v;
    }
    __syncthreads();
    int w = t >> 5, lane = t & 31;
    int bb = row0 >> 11, n0 = row0 & (N_ - 1);
    #pragma unroll
    for (int jj = 0; jj < 4; jj++) {
        int ff = w*4 + jj;
        float v = Ysm[lane][ff];
        __nv_bfloat16 h = __float2bfloat16(v);
        size_t ti = ((size_t)bb*HID_ + ff)*N_ + n0 + lane;
        Thi[ti] = h;
        Tlo[ti] = __float2bfloat16(v - __bfloat162float(h));
    }
}

// ---------------- HMMA GEMM: fp32 A stream, split-k warps, fused epilogue ----------------
#define BM 64
#define BK 64
#define NT (N_/BK)
#define NSTAGE 4
#define AFP_OFF 0
#define BHI_OFF 16384
#define BLO_OFF 20480
#define STGSZ   24576
#define WSM_OFF (NSTAGE*STGSZ)
#define GEMM_SMEM (WSM_OFF + 4096)            // 100 KB -> 2 CTAs/SM

__device__ __forceinline__ void fill_async(char* stage, int t, const float* Afp,
                                           const __nv_bfloat16* Bh, const __nv_bfloat16* Bl,
                                           int k0) {
    #pragma unroll
    for (int i = 0; i < 4; i++) {
        int c = t + i*256;
        int r = c >> 4, ch = c & 15;
        int x = (ch*16) ^ ((r & 7) << 4);
        cp16(stage + AFP_OFF + r*256 + x, Afp + (size_t)r*N_ + k0 + ch*4);
    }
    {
        int r = t >> 3, seg = t & 7;
        int x = (seg*16) ^ ((r & 7) << 4);
        cp16(stage + BHI_OFF + r*128 + x, Bh + (size_t)r*N_ + k0 + seg*8);
        cp16(stage + BLO_OFF + r*128 + x, Bl + (size_t)r*N_ + k0 + seg*8);
    }
}

__global__ void __launch_bounds__(256, 2) gemm_kernel(
    const float* __restrict__ A,
    const __nv_bfloat16* __restrict__ BThi, const __nv_bfloat16* __restrict__ BTli,
    const float* __restrict__ Yin, const float* __restrict__ bias,
    const float* __restrict__ Wnext,
    float* __restrict__ Yout,
    __nv_bfloat16* __restrict__ Thi_out, __nv_bfloat16* __restrict__ Tlo_out) {
    extern __shared__ char sm[];
    int t = threadIdx.x;
    int lane = t & 31, w = t >> 5;
    int wk = w & 1, wm = w >> 1;               // split-k: warp owns 16 rows x all 32 cols, half the k
    int g = lane >> 2, t4 = lane & 3;
    int b = blockIdx.y, row0 = blockIdx.x * BM;

    const float* Afp = A + (size_t)b*N_*N_ + (size_t)row0*N_;
    const __nv_bfloat16* Bh = BThi + (size_t)b*HID_*N_;
    const __nv_bfloat16* Bl = BTli + (size_t)b*HID_*N_;

    float* wsm = (float*)(sm + WSM_OFF);
    if (Wnext) for (int i = t; i < HID_*HID_; i += 256) wsm[i] = Wnext[i];

    // B ldmatrix addressing: two 16-row groups (n 0-15 and n 16-31)
    int row_in = lane & 15;
    int half = lane >> 4;
    int swz = (row_in & 7) << 4;
    uint32_t smb = (uint32_t)__cvta_generic_to_shared(sm);
    uint32_t boff0 = row_in * 128;
    uint32_t boff1 = (16 + row_in) * 128;

    // A fp32 fragment addressing
    int rowA0 = wm*16 + g;
    uint32_t abase0 = rowA0 * 256;
    uint32_t abase1 = (rowA0 + 8) * 256;
    uint32_t asw = (uint32_t)(g << 4);
    uint32_t acol = (uint32_t)(8 * t4);

    float acc[4][4];
    #pragma unroll
    for (int nt = 0; nt < 4; nt++)
        #pragma unroll
        for (int i = 0; i < 4; i++) acc[nt][i] = 0.f;

    #pragma unroll
    for (int p = 0; p < NSTAGE-1; p++) {
        fill_async(sm + p*STGSZ, t, Afp, Bh, Bl, p*BK);
        asm volatile("cp.async.commit_group;" ::: "memory");
    }

    for (int kt = 0; kt < NT; kt++) {
        asm volatile("cp.async.wait_group %0;" :: "n"(NSTAGE-2) : "memory");
        __syncthreads();
        if (kt + NSTAGE - 1 < NT)
            fill_async(sm + ((kt + NSTAGE - 1) % NSTAGE)*STGSZ, t, Afp, Bh, Bl, (kt + NSTAGE - 1)*BK);
        asm volatile("cp.async.commit_group;" ::: "memory");

        uint32_t stg = smb + (kt % NSTAGE)*STGSZ;
        char* stgc = sm + (kt % NSTAGE)*STGSZ;
        #pragma unroll
        for (int c = 0; c < 2; c++) {
            int kk = wk*2 + c;                 // this warp's k-chunk
            // A: fp32 fragment -> bf16 hi/lo in regs
            uint32_t c0 = (uint32_t)(kk*64) + acol;
            uint32_t c1 = c0 + 32;
            float2 fa0 = *(float2*)(stgc + AFP_OFF + abase0 + (c0 ^ asw));
            float2 fa1 = *(float2*)(stgc + AFP_OFF + abase1 + (c0 ^ asw));
            float2 fa2 = *(float2*)(stgc + AFP_OFF + abase0 + (c1 ^ asw));
            float2 fa3 = *(float2*)(stgc + AFP_OFF + abase1 + (c1 ^ asw));
            uint32_t ah[4], al[4];
            cvt_pair(fa0, ah[0], al[0]);
            cvt_pair(fa1, ah[1], al[1]);
            cvt_pair(fa2, ah[2], al[2]);
            cvt_pair(fa3, ah[3], al[3]);
            // B: all 32 n columns
            uint32_t koff = (uint32_t)((kk*32 + half*16) ^ swz);
            uint32_t bhA[4], blA[4], bhB[4], blB[4];
            ldsm4(bhA, stg + BHI_OFF + boff0 + koff);
            ldsm4(blA, stg + BLO_OFF + boff0 + koff);
            ldsm4(bhB, stg + BHI_OFF + boff1 + koff);
            ldsm4(blB, stg + BLO_OFF + boff1 + koff);
            uint32_t bhr[4][2] = {{bhA[0],bhA[2]},{bhA[1],bhA[3]},{bhB[0],bhB[2]},{bhB[1],bhB[3]}};
            uint32_t blr[4][2] = {{blA[0],blA[2]},{blA[1],blA[3]},{blB[0],blB[2]},{blB[1],blB[3]}};
            #pragma unroll
            for (int nt = 0; nt < 4; nt++) {
                mma16816(acc[nt], ah, bhr[nt]);
                mma16816(acc[nt], ah, blr[nt]);
                mma16816(acc[nt], al, bhr[nt]);
            }
        }
    }

    // ---- k-split reduction (wk=1 partials into wk=0) ----
    __syncthreads();
    float* red = (float*)sm;                   // 2048 floats = 8 KB, lane-contiguous layout
    if (wk == 1) {
        int col = wm*32 + lane;
        #pragma unroll
        for (int nt = 0; nt < 4; nt++)
            #pragma unroll
            for (int i = 0; i < 4; i++)
                red[(nt*4 + i)*128 + col] = acc[nt][i];
    }
    __syncthreads();
    if (wk == 0) {
        int col = wm*32 + lane;
        #pragma unroll
        for (int nt = 0; nt < 4; nt++)
            #pragma unroll
            for (int i = 0; i < 4; i++)
                acc[nt][i] += red[(nt*4 + i)*128 + col];
    }
    __syncthreads();

    const float* Yg = Yin + (size_t)b*N_*HID_;
    float* Hs = (float*)sm;                    // [64][34] fp32

    if (Wnext) {
        if (wk == 0) {
            int rL = wm*16 + g;
            int rH = rL + 8;
            int rowL = row0 + rL, rowH = row0 + rH;
            float dmL = g_dm[b*N_ + rowL], adL = g_add[b*N_ + rowL];
            float dmH = g_dm[b*N_ + rowH], adH = g_add[b*N_ + rowH];
            #pragma unroll
            for (int nt = 0; nt < 4; nt++) {
                int col = nt*8 + 2*t4;
                float2 bs = *(const float2*)&bias[col];
                float2 yL = *(const float2*)&Yg[(size_t)rowL*HID_ + col];
                float2 yH = *(const float2*)&Yg[(size_t)rowH*HID_ + col];
                Hs[rL*34 + col]     = fmaxf(fmaf(dmL, acc[nt][0] + adL*yL.x, bs.x), 0.f);
                Hs[rL*34 + col + 1] = fmaxf(fmaf(dmL, acc[nt][1] + adL*yL.y, bs.y), 0.f);
                Hs[rH*34 + col]     = fmaxf(fmaf(dmH, acc[nt][2] + adH*yH.x, bs.x), 0.f);
                Hs[rH*34 + col + 1] = fmaxf(fmaf(dmH, acc[nt][3] + adH*yH.y, bs.y), 0.f);
            }
        }
        __syncthreads();
        int f = t & 31, rb = (t >> 5) * 8;
        float acc2[8];
        #pragma unroll
        for (int r = 0; r < 8; r++) acc2[r] = 0.f;
        #pragma unroll
        for (int k = 0; k < HID_; k++) {
            float wv = wsm[k*HID_ + f];
            #pragma unroll
            for (int r = 0; r < 8; r++) acc2[r] += Hs[(rb + r)*34 + k] * wv;
        }
        int n0g = b*N_ + row0 + rb;
        uint32_t hp[4], lp[4];
        unsigned short hh[8], ll[8];
        #pragma unroll
        for (int r = 0; r < 8; r++) {
            float v = g_dm[n0g + r] * acc2[r];
            Yout[(size_t)(n0g + r)*HID_ + f] = v;
            __nv_bfloat16 hb = __float2bfloat16(v);
            hh[r] = bf16u(hb);
            ll[r] = bf16u(__float2bfloat16(v - __bfloat162float(hb)));
        }
        #pragma unroll
        for (int j = 0; j < 4; j++) {
            hp[j] = (uint32_t)hh[2*j] | ((uint32_t)hh[2*j+1] << 16);
            lp[j] = (uint32_t)ll[2*j] | ((uint32_t)ll[2*j+1] << 16);
        }
        size_t to = ((size_t)b*HID_ + f)*N_ + row0 + rb;
        *(uint4*)(Thi_out + to) = *(uint4*)&hp[0];
        *(uint4*)(Tlo_out + to) = *(uint4*)&lp[0];
    } else {
        if (wk == 0) {
            int rowL = row0 + wm*16 + g;
            int rowH = rowL + 8;
            float dmL = g_dm[b*N_ + rowL], adL = g_add[b*N_ + rowL];
            float dmH = g_dm[b*N_ + rowH], adH = g_add[b*N_ + rowH];
            #pragma unroll
            for (int nt = 0; nt < 4; nt++) {
                int col = nt*8 + 2*t4;
                float2 bs = *(const float2*)&bias[col];
                float2 yL = *(const float2*)&Yg[(size_t)rowL*HID_ + col];
                float2 yH = *(const float2*)&Yg[(size_t)rowH*HID_ + col];
                float m0 = fmaxf(fmaf(dmL, acc[nt][0] + adL*yL.x, bs.x),
                                 fmaf(dmH, acc[nt][2] + adH*yH.x, bs.x));
                float m1 = fmaxf(fmaf(dmL, acc[nt][1] + adL*yL.y, bs.y),
                                 fmaf(dmH, acc[nt][3] + adH*yH.y, bs.y));
                atomicMax((int*)&g_pool[b*HID_ + col],     __float_as_int(fmaxf(m0, 0.f)));
                atomicMax((int*)&g_pool[b*HID_ + col + 1], __float_as_int(fmaxf(m1, 0.f)));
            }
        }
    }
}

// ---------------- MLP head ----------------
__global__ void head_kernel(const float* __restrict__ Wf1, const float* __restrict__ bf1,
                            const float* __restrict__ Wf2, const float* __restrict__ bf2,
                            float* __restrict__ out) {
    int w = threadIdx.x >> 5, lane = threadIdx.x & 31;
    float o = 0.f;
    #pragma unroll
    for (int ii = 0; ii < 2; ii++) {
        int j = lane + 32*ii;
        float s = bf1[j];
        #pragma unroll
        for (int f = 0; f < HID_; f++) s += g_pool[w*HID_ + f] * Wf1[f*2*HID_ + j];
        o += fmaxf(s, 0.f) * Wf2[j];
    }
    #pragma unroll
    for (int off = 16; off; off >>= 1) o += __shfl_xor_sync(0xffffffffu, o, off);
    if (lane == 0) out[w] = o + bf2[0];
}

// ---------------- launch ----------------
extern "C" void kernel_launch(void* const* d_in, const int* in_sizes, int n_in,
                              void* d_out, int out_size) {
    const float* x   = (const float*)d_in[0];
    const float* a   = (const float*)d_in[1];
    const float* W1  = (const float*)d_in[2];
    const float* b1  = (const float*)d_in[3];
    const float* W2  = (const float*)d_in[4];
    const float* b2  = (const float*)d_in[5];
    const float* W3  = (const float*)d_in[6];
    const float* b3  = (const float*)d_in[7];
    const float* Wf1 = (const float*)d_in[8];
    const float* bf1 = (const float*)d_in[9];
    const float* Wf2 = (const float*)d_in[10];
    const float* bf2 = (const float*)d_in[11];
    float* out = (float*)d_out;

    cudaFuncSetAttribute(gemm_kernel, cudaFuncAttributeMaxDynamicSharedMemorySize, GEMM_SMEM);

    float *Ya, *Yb;  __nv_bfloat16 *Tha, *Tla, *Thb, *Tlb;
    cudaGetSymbolAddress((void**)&Ya,  g_Ya);
    cudaGetSymbolAddress((void**)&Yb,  g_Yb);
    cudaGetSymbolAddress((void**)&Tha, g_Thi_a);
    cudaGetSymbolAddress((void**)&Tla, g_Tlo_a);
    cudaGetSymbolAddress((void**)&Thb, g_Thi_b);
    cudaGetSymbolAddress((void**)&Tlb, g_Tlo_b);

    dim3 gg(N_/BM, B_);

    deg_kernel<<<BN_TOTAL/8, 256>>>(a);
    y1_kernel<<<BN_TOTAL/32, 256>>>(x, W1, Ya, Tha, Tla);
    gemm_kernel<<<gg, 256, GEMM_SMEM>>>(a, Tha, Tla, Ya, b1, W2, Yb, Thb, Tlb);
    gemm_kernel<<<gg, 256, GEMM_SMEM>>>(a, Thb, Tlb, Yb, b2, W3, Ya, Tha, Tla);
    gemm_kernel<<<gg, 256, GEMM_SMEM>>>(a, Tha, Tla, Ya, b3, nullptr, nullptr, nullptr, nullptr);
    head_kernel<<<1, 256>>>(Wf1, bf1, Wf2, bf2, out);
}

// round 16
// speedup vs baseline: 1.4882x; 1.0047x over previous
#include <cuda_runtime.h>
#include <cuda_bf16.h>
#include <cstdint>

#define B_ 8
#define N_ 2048
#define F_ 64
#define HID_ 32
#define BN_TOTAL (B_*N_)

// ---------------- scratch ----------------
__device__ float g_dm[BN_TOTAL];
__device__ float g_add[BN_TOTAL];
__device__ float g_Ya[BN_TOTAL*HID_];
__device__ float g_Yb[BN_TOTAL*HID_];
__device__ float g_pool[B_*HID_];
__device__ __nv_bfloat16 g_Thi_a[B_*HID_*N_];
__device__ __nv_bfloat16 g_Tlo_a[B_*HID_*N_];
__device__ __nv_bfloat16 g_Thi_b[B_*HID_*N_];
__device__ __nv_bfloat16 g_Tlo_b[B_*HID_*N_];

// ---------------- helpers ----------------
__device__ __forceinline__ void mma16816(float* c, const uint32_t* a, const uint32_t* b) {
    asm volatile("mma.sync.aligned.m16n8k16.row.col.f32.bf16.bf16.f32 "
        "{%0,%1,%2,%3}, {%4,%5,%6,%7}, {%8,%9}, {%0,%1,%2,%3};"
        : "+f"(c[0]), "+f"(c[1]), "+f"(c[2]), "+f"(c[3])
        : "r"(a[0]), "r"(a[1]), "r"(a[2]), "r"(a[3]), "r"(b[0]), "r"(b[1]));
}
__device__ __forceinline__ void ldsm4(uint32_t* r, uint32_t addr) {
    asm volatile("ldmatrix.sync.aligned.m8n8.x4.shared.b16 {%0,%1,%2,%3}, [%4];"
        : "=r"(r[0]), "=r"(r[1]), "=r"(r[2]), "=r"(r[3]) : "r"(addr));
}
__device__ __forceinline__ unsigned short bf16u(__nv_bfloat16 h) { return *(unsigned short*)&h; }
__device__ __forceinline__ void cp16(void* dst, const void* src) {
    uint32_t s = (uint32_t)__cvta_generic_to_shared(dst);
    asm volatile("cp.async.cg.shared.global [%0], [%1], 16;" :: "r"(s), "l"(src));
}
__device__ __forceinline__ float4 ldcs4(const float4* p) {
    float4 v;
    asm volatile("ld.global.cs.v4.f32 {%0,%1,%2,%3}, [%4];"
        : "=f"(v.x), "=f"(v.y), "=f"(v.z), "=f"(v.w) : "l"(p));
    return v;
}
__device__ __forceinline__ void cvt_pair(float2 f, uint32_t& hi, uint32_t& lo) {
    asm("cvt.rn.bf16x2.f32 %0, %1, %2;" : "=r"(hi) : "f"(f.y), "f"(f.x));
    float h0 = __uint_as_float(hi << 16);
    float h1 = __uint_as_float(hi & 0xffff0000u);
    float l0 = f.x - h0, l1 = f.y - h1;
    asm("cvt.rn.bf16x2.f32 %0, %1, %2;" : "=r"(lo) : "f"(l1), "f"(l0));
}

// ---------------- degree + normalization only ----------------
__global__ void deg_kernel(const float* __restrict__ a) {
    int row  = blockIdx.x * 8 + (threadIdx.x >> 5);
    int lane = threadIdx.x & 31;
    const float4* ar4 = (const float4*)(a + (size_t)row * N_);
    float s = 0.f;
    #pragma unroll
    for (int j = 0; j < N_/128; j++) {
        float4 v = ldcs4(&ar4[lane + j*32]);
        s += (v.x + v.y) + (v.z + v.w);
    }
    #pragma unroll
    for (int o = 16; o; o >>= 1) s += __shfl_xor_sync(0xffffffffu, s, o);
    if (lane == 0) {
        int i = row & (N_ - 1);
        float diag = a[(size_t)row * N_ + i];
        float add  = (fabsf(diag) < 1e-7f) ? 1.0f : 0.0f;
        g_add[row] = add;
        g_dm[row]  = 1.0f / sqrtf(s + add);
    }
}

// ---------------- Y1 = dm .* (x @ W1) ----------------
__global__ void y1_kernel(const float* __restrict__ Hin, const float* __restrict__ W,
                          float* __restrict__ Yout,
                          __nv_bfloat16* __restrict__ Thi, __nv_bfloat16* __restrict__ Tlo) {
    const int K = F_;
    __shared__ float Ws[K*HID_];
    __shared__ float Hs[32][K];
    __shared__ float Ysm[32][33];
    int t = threadIdx.x;
    int row0 = blockIdx.x * 32;
    for (int i = t; i < K*HID_/4; i += 256) ((float4*)Ws)[i] = ((const float4*)W)[i];
    for (int i = t; i < 32*K/4;  i += 256) ((float4*)Hs)[i] = ((const float4*)(Hin + (size_t)row0*K))[i];
    __syncthreads();
    int rb = (t >> 5) * 4, f = t & 31;
    float acc[4] = {0.f, 0.f, 0.f, 0.f};
    #pragma unroll
    for (int k = 0; k < K; k++) {
        float wv = Ws[k*HID_ + f];
        acc[0] += Hs[rb+0][k] * wv;
        acc[1] += Hs[rb+1][k] * wv;
        acc[2] += Hs[rb+2][k] * wv;
        acc[3] += Hs[rb+3][k] * wv;
    }
    #pragma unroll
    for (int j = 0; j < 4; j++) {
        int row = row0 + rb + j;
        float v = g_dm[row] * acc[j];
        Yout[(size_t)row*HID_ + f] = v;
        Ysm[rb + j][f] = v;
    }
    __syncthreads();
    int w = t >> 5, lane = t & 31;
    int bb = row0 >> 11, n0 = row0 & (N_ - 1);
    #pragma unroll
    for (int jj = 0; jj < 4; jj++) {
        int ff = w*4 + jj;
        float v = Ysm[lane][ff];
        __nv_bfloat16 h = __float2bfloat16(v);
        size_t ti = ((size_t)bb*HID_ + ff)*N_ + n0 + lane;
        Thi[ti] = h;
        Tlo[ti] = __float2bfloat16(v - __bfloat162float(h));
    }
}

// ---------------- HMMA GEMM: fp32 A stream, split-k warps, 3 CTAs/SM ----------------
#define BM 64
#define BK 64
#define NT (N_/BK)
#define NSTAGE 3
#define AFP_OFF 0
#define BHI_OFF 16384
#define BLO_OFF 20480
#define STGSZ   24576
#define GEMM_SMEM (NSTAGE*STGSZ)              // 72 KB -> 3 CTAs/SM

__device__ __forceinline__ void fill_async(char* stage, int t, const float* Afp,
                                           const __nv_bfloat16* Bh, const __nv_bfloat16* Bl,
                                           int k0) {
    #pragma unroll
    for (int i = 0; i < 4; i++) {
        int c = t + i*256;
        int r = c >> 4, ch = c & 15;
        int x = (ch*16) ^ ((r & 7) << 4);
        cp16(stage + AFP_OFF + r*256 + x, Afp + (size_t)r*N_ + k0 + ch*4);
    }
    {
        int r = t >> 3, seg = t & 7;
        int x = (seg*16) ^ ((r & 7) << 4);
        cp16(stage + BHI_OFF + r*128 + x, Bh + (size_t)r*N_ + k0 + seg*8);
        cp16(stage + BLO_OFF + r*128 + x, Bl + (size_t)r*N_ + k0 + seg*8);
    }
}

__global__ void __launch_bounds__(256, 3) gemm_kernel(
    const float* __restrict__ A,
    const __nv_bfloat16* __restrict__ BThi, const __nv_bfloat16* __restrict__ BTli,
    const float* __restrict__ Yin, const float* __restrict__ bias,
    const float* __restrict__ Wnext,
    float* __restrict__ Yout,
    __nv_bfloat16* __restrict__ Thi_out, __nv_bfloat16* __restrict__ Tlo_out) {
    extern __shared__ char sm[];
    int t = threadIdx.x;
    int lane = t & 31, w = t >> 5;
    int wk = w & 1, wm = w >> 1;               // split-k: warp owns 16 rows x all 32 cols, half the k
    int g = lane >> 2, t4 = lane & 3;
    int b = blockIdx.y, row0 = blockIdx.x * BM;

    const float* Afp = A + (size_t)b*N_*N_ + (size_t)row0*N_;
    const __nv_bfloat16* Bh = BThi + (size_t)b*HID_*N_;
    const __nv_bfloat16* Bl = BTli + (size_t)b*HID_*N_;

    // B ldmatrix addressing: two 16-row groups (n 0-15 and n 16-31)
    int row_in = lane & 15;
    int half = lane >> 4;
    int swz = (row_in & 7) << 4;
    uint32_t smb = (uint32_t)__cvta_generic_to_shared(sm);
    uint32_t boff0 = row_in * 128;
    uint32_t boff1 = (16 + row_in) * 128;

    // A fp32 fragment addressing
    int rowA0 = wm*16 + g;
    uint32_t abase0 = rowA0 * 256;
    uint32_t abase1 = (rowA0 + 8) * 256;
    uint32_t asw = (uint32_t)(g << 4);
    uint32_t acol = (uint32_t)(8 * t4);

    float acc[4][4];
    #pragma unroll
    for (int nt = 0; nt < 4; nt++)
        #pragma unroll
        for (int i = 0; i < 4; i++) acc[nt][i] = 0.f;

    #pragma unroll
    for (int p = 0; p < NSTAGE-1; p++) {
        fill_async(sm + p*STGSZ, t, Afp, Bh, Bl, p*BK);
        asm volatile("cp.async.commit_group;" ::: "memory");
    }

    for (int kt = 0; kt < NT; kt++) {
        asm volatile("cp.async.wait_group %0;" :: "n"(NSTAGE-2) : "memory");
        __syncthreads();
        if (kt + NSTAGE - 1 < NT)
            fill_async(sm + ((kt + NSTAGE - 1) % NSTAGE)*STGSZ, t, Afp, Bh, Bl, (kt + NSTAGE - 1)*BK);
        asm volatile("cp.async.commit_group;" ::: "memory");

        uint32_t stg = smb + (kt % NSTAGE)*STGSZ;
        char* stgc = sm + (kt % NSTAGE)*STGSZ;
        #pragma unroll
        for (int c = 0; c < 2; c++) {
            int kk = wk*2 + c;                 // this warp's k-chunk
            // A: fp32 fragment -> bf16 hi/lo in regs
            uint32_t c0 = (uint32_t)(kk*64) + acol;
            uint32_t c1 = c0 + 32;
            float2 fa0 = *(float2*)(stgc + AFP_OFF + abase0 + (c0 ^ asw));
            float2 fa1 = *(float2*)(stgc + AFP_OFF + abase1 + (c0 ^ asw));
            float2 fa2 = *(float2*)(stgc + AFP_OFF + abase0 + (c1 ^ asw));
            float2 fa3 = *(float2*)(stgc + AFP_OFF + abase1 + (c1 ^ asw));
            uint32_t ah[4], al[4];
            cvt_pair(fa0, ah[0], al[0]);
            cvt_pair(fa1, ah[1], al[1]);
            cvt_pair(fa2, ah[2], al[2]);
            cvt_pair(fa3, ah[3], al[3]);
            // B: all 32 n columns
            uint32_t koff = (uint32_t)((kk*32 + half*16) ^ swz);
            uint32_t bhA[4], blA[4], bhB[4], blB[4];
            ldsm4(bhA, stg + BHI_OFF + boff0 + koff);
            ldsm4(blA, stg + BLO_OFF + boff0 + koff);
            ldsm4(bhB, stg + BHI_OFF + boff1 + koff);
            ldsm4(blB, stg + BLO_OFF + boff1 + koff);
            uint32_t bhr[4][2] = {{bhA[0],bhA[2]},{bhA[1],bhA[3]},{bhB[0],bhB[2]},{bhB[1],bhB[3]}};
            uint32_t blr[4][2] = {{blA[0],blA[2]},{blA[1],blA[3]},{blB[0],blB[2]},{blB[1],blB[3]}};
            #pragma unroll
            for (int nt = 0; nt < 4; nt++) {
                mma16816(acc[nt], ah, bhr[nt]);
                mma16816(acc[nt], ah, blr[nt]);
                mma16816(acc[nt], al, bhr[nt]);
            }
        }
    }

    // ---- k-split reduction (wk=1 partials into wk=0) ----
    __syncthreads();
    float* red = (float*)sm;                   // 2048 floats = 8 KB, lane-contiguous layout
    if (wk == 1) {
        int col = wm*32 + lane;
        #pragma unroll
        for (int nt = 0; nt < 4; nt++)
            #pragma unroll
            for (int i = 0; i < 4; i++)
                red[(nt*4 + i)*128 + col] = acc[nt][i];
    }
    __syncthreads();
    if (wk == 0) {
        int col = wm*32 + lane;
        #pragma unroll
        for (int nt = 0; nt < 4; nt++)
            #pragma unroll
            for (int i = 0; i < 4; i++)
                acc[nt][i] += red[(nt*4 + i)*128 + col];
    }
    __syncthreads();

    const float* Yg = Yin + (size_t)b*N_*HID_;
    float* Hs = (float*)sm;                    // [64][34] fp32

    if (Wnext) {
        if (wk == 0) {
            int rL = wm*16 + g;
            int rH = rL + 8;
            int rowL = row0 + rL, rowH = row0 + rH;
            float dmL = g_dm[b*N_ + rowL], adL = g_add[b*N_ + rowL];
            float dmH = g_dm[b*N_ + rowH], adH = g_add[b*N_ + rowH];
            #pragma unroll
            for (int nt = 0; nt < 4; nt++) {
                int col = nt*8 + 2*t4;
                float2 bs = *(const float2*)&bias[col];
                float2 yL = *(const float2*)&Yg[(size_t)rowL*HID_ + col];
                float2 yH = *(const float2*)&Yg[(size_t)rowH*HID_ + col];
                Hs[rL*34 + col]     = fmaxf(fmaf(dmL, acc[nt][0] + adL*yL.x, bs.x), 0.f);
                Hs[rL*34 + col + 1] = fmaxf(fmaf(dmL, acc[nt][1] + adL*yL.y, bs.y), 0.f);
                Hs[rH*34 + col]     = fmaxf(fmaf(dmH, acc[nt][2] + adH*yH.x, bs.x), 0.f);
                Hs[rH*34 + col + 1] = fmaxf(fmaf(dmH, acc[nt][3] + adH*yH.y, bs.y), 0.f);
            }
        }
        __syncthreads();
        int f = t & 31, rb = (t >> 5) * 8;
        float acc2[8];
        #pragma unroll
        for (int r = 0; r < 8; r++) acc2[r] = 0.f;
        #pragma unroll
        for (int k = 0; k < HID_; k++) {
            float wv = __ldg(&Wnext[k*HID_ + f]);
            #pragma unroll
            for (int r = 0; r < 8; r++) acc2[r] += Hs[(rb + r)*34 + k] * wv;
        }
        int n0g = b*N_ + row0 + rb;
        uint32_t hp[4], lp[4];
        unsigned short hh[8], ll[8];
        #pragma unroll
        for (int r = 0; r < 8; r++) {
            float v = g_dm[n0g + r] * acc2[r];
            Yout[(size_t)(n0g + r)*HID_ + f] = v;
            __nv_bfloat16 hb = __float2bfloat16(v);
            hh[r] = bf16u(hb);
            ll[r] = bf16u(__float2bfloat16(v - __bfloat162float(hb)));
        }
        #pragma unroll
        for (int j = 0; j < 4; j++) {
            hp[j] = (uint32_t)hh[2*j] | ((uint32_t)hh[2*j+1] << 16);
            lp[j] = (uint32_t)ll[2*j] | ((uint32_t)ll[2*j+1] << 16);
        }
        size_t to = ((size_t)b*HID_ + f)*N_ + row0 + rb;
        *(uint4*)(Thi_out + to) = *(uint4*)&hp[0];
        *(uint4*)(Tlo_out + to) = *(uint4*)&lp[0];
    } else {
        if (wk == 0) {
            int rowL = row0 + wm*16 + g;
            int rowH = rowL + 8;
            float dmL = g_dm[b*N_ + rowL], adL = g_add[b*N_ + rowL];
            float dmH = g_dm[b*N_ + rowH], adH = g_add[b*N_ + rowH];
            #pragma unroll
            for (int nt = 0; nt < 4; nt++) {
                int col = nt*8 + 2*t4;
                float2 bs = *(const float2*)&bias[col];
                float2 yL = *(const float2*)&Yg[(size_t)rowL*HID_ + col];
                float2 yH = *(const float2*)&Yg[(size_t)rowH*HID_ + col];
                float m0 = fmaxf(fmaf(dmL, acc[nt][0] + adL*yL.x, bs.x),
                                 fmaf(dmH, acc[nt][2] + adH*yH.x, bs.x));
                float m1 = fmaxf(fmaf(dmL, acc[nt][1] + adL*yL.y, bs.y),
                                 fmaf(dmH, acc[nt][3] + adH*yH.y, bs.y));
                atomicMax((int*)&g_pool[b*HID_ + col],     __float_as_int(fmaxf(m0, 0.f)));
                atomicMax((int*)&g_pool[b*HID_ + col + 1], __float_as_int(fmaxf(m1, 0.f)));
            }
        }
    }
}

// ---------------- MLP head ----------------
__global__ void head_kernel(const float* __restrict__ Wf1, const float* __restrict__ bf1,
                            const float* __restrict__ Wf2, const float* __restrict__ bf2,
                            float* __restrict__ out) {
    int w = threadIdx.x >> 5, lane = threadIdx.x & 31;
    float o = 0.f;
    #pragma unroll
    for (int ii = 0; ii < 2; ii++) {
        int j = lane + 32*ii;
        float s = bf1[j];
        #pragma unroll
        for (int f = 0; f < HID_; f++) s += g_pool[w*HID_ + f] * Wf1[f*2*HID_ + j];
        o += fmaxf(s, 0.f) * Wf2[j];
    }
    #pragma unroll
    for (int off = 16; off; off >>= 1) o += __shfl_xor_sync(0xffffffffu, o, off);
    if (lane == 0) out[w] = o + bf2[0];
}

// ---------------- launch ----------------
extern "C" void kernel_launch(void* const* d_in, const int* in_sizes, int n_in,
                              void* d_out, int out_size) {
    const float* x   = (const float*)d_in[0];
    const float* a   = (const float*)d_in[1];
    const float* W1  = (const float*)d_in[2];
    const float* b1  = (const float*)d_in[3];
    const float* W2  = (const float*)d_in[4];
    const float* b2  = (const float*)d_in[5];
    const float* W3  = (const float*)d_in[6];
    const float* b3  = (const float*)d_in[7];
    const float* Wf1 = (const float*)d_in[8];
    const float* bf1 = (const float*)d_in[9];
    const float* Wf2 = (const float*)d_in[10];
    const float* bf2 = (const float*)d_in[11];
    float* out = (float*)d_out;

    cudaFuncSetAttribute(gemm_kernel, cudaFuncAttributeMaxDynamicSharedMemorySize, GEMM_SMEM);

    float *Ya, *Yb;  __nv_bfloat16 *Tha, *Tla, *Thb, *Tlb;
    cudaGetSymbolAddress((void**)&Ya,  g_Ya);
    cudaGetSymbolAddress((void**)&Yb,  g_Yb);
    cudaGetSymbolAddress((void**)&Tha, g_Thi_a);
    cudaGetSymbolAddress((void**)&Tla, g_Tlo_a);
    cudaGetSymbolAddress((void**)&Thb, g_Thi_b);
    cudaGetSymbolAddress((void**)&Tlb, g_Tlo_b);

    dim3 gg(N_/BM, B_);

    deg_kernel<<<BN_TOTAL/8, 256>>>(a);
    y1_kernel<<<BN_TOTAL/32, 256>>>(x, W1, Ya, Tha, Tla);
    gemm_kernel<<<gg, 256, GEMM_SMEM>>>(a, Tha, Tla, Ya, b1, W2, Yb, Thb, Tlb);
    gemm_kernel<<<gg, 256, GEMM_SMEM>>>(a, Thb, Tlb, Yb, b2, W3, Ya, Tha, Tla);
    gemm_kernel<<<gg, 256, GEMM_SMEM>>>(a, Tha, Tla, Ya, b3, nullptr, nullptr, nullptr, nullptr);
    head_kernel<<<1, 256>>>(Wf1, bf1, Wf2, bf2, out);
}